// round 11
// baseline (speedup 1.0000x reference)
#include <cuda_runtime.h>
#include <cuda_bf16.h>

#define T_STEPS 512
#define NB 14
#define NBLK ((2048 + NB - 1) / NB)   // 147 blocks, 1 CTA/SM
#define NTHREADS 512                  // 4 roles x (64 j x 2 k-halves)

typedef unsigned long long ull;

__device__ __forceinline__ ull ffma2(ull a, ull b, ull c) {
    ull d;
    asm("fma.rn.f32x2 %0, %1, %2, %3;" : "=l"(d) : "l"(a), "l"(b), "l"(c));
    return d;
}
__device__ __forceinline__ ull add2(ull a, ull b) {
    ull d;
    asm("add.rn.f32x2 %0, %1, %2;" : "=l"(d) : "l"(a), "l"(b));
    return d;
}
__device__ __forceinline__ float hsum2(ull v) {
    float lo, hi;
    asm("mov.b64 {%0, %1}, %2;" : "=f"(lo), "=f"(hi) : "l"(v));
    return lo + hi;
}
// branch-free tanh: 1 - 2/(exp(2s)+1) via ex2/rcp approx (abs err ~1e-7)
__device__ __forceinline__ float tanh_fast(float s) {
    float e;
    asm("ex2.approx.f32 %0, %1;" : "=f"(e) : "f"(s * 2.8853900817779268f));
    float r;
    asm("rcp.approx.f32 %0, %1;" : "=f"(r) : "f"(e + 1.0f));
    return __fmaf_rn(-2.0f, r, 1.0f);
}

__global__ __launch_bounds__(NTHREADS, 1)
void rnn_ws_kernel(const float* __restrict__ x,
                   const float* __restrict__ Wih0,
                   const float* __restrict__ Whh0,
                   const float* __restrict__ bih0,
                   const float* __restrict__ bhh0,
                   const float* __restrict__ Wih1,
                   const float* __restrict__ Whh1,
                   const float* __restrict__ bih1,
                   const float* __restrict__ bhh1,
                   const float* __restrict__ fcw,
                   const float* __restrict__ fcb,
                   float* __restrict__ out)
{
    // state buffers (parity: value at step s lives in buf[s&1])
    __shared__ __align__(16) float h0buf[2][NB][64];
    __shared__ __align__(16) float h1buf[2][NB][64];
    __shared__ __align__(16) float cbuf[2][NB][64];
    __shared__ __align__(16) float xbuf[2][NB][8];
    // k-half partial-sum exchange (packed f32x2)
    __shared__ __align__(16) ull p0[NB][64];   // layer0
    __shared__ __align__(16) ull p1[NB][64];   // Wih1.h0
    __shared__ __align__(16) ull p2[NB][64];   // Whh1.h1

    const int tid  = threadIdx.x;
    const int j    = tid & 63;
    const int kh   = (tid >> 6) & 1;          // k-half: [0..31] or [32..63]
    const int role = tid >> 7;                // 0:L0(b0-6) 1:Wih1 2:Whh1+comb 3:L0(b7-13)
    const int b0   = blockIdx.x * NB;

    // ---- weights: this thread's half-row, packed f32x2 ----
    ull wv[16];
    {
        const float* ws = (role == 1) ? (Wih1 + j * 64)
                        : (role == 2) ? (Whh1 + j * 64)
                                      : (Whh0 + j * 64);
#pragma unroll
        for (int i = 0; i < 8; ++i) {
            ulonglong2 v = *reinterpret_cast<const ulonglong2*>(ws + kh * 32 + i * 4);
            wv[2 * i] = v.x; wv[2 * i + 1] = v.y;
        }
    }
    ull wx[4] = {0, 0, 0, 0};
    float bias0 = 0.f, bias1 = 0.f;
    if (role == 0 || role == 3) {
        ulonglong2 v0 = *reinterpret_cast<const ulonglong2*>(Wih0 + j * 8);
        ulonglong2 v1 = *reinterpret_cast<const ulonglong2*>(Wih0 + j * 8 + 4);
        wx[0] = v0.x; wx[1] = v0.y; wx[2] = v1.x; wx[3] = v1.y;
        bias0 = bih0[j] + bhh0[j];
    }
    if (role == 2) bias1 = bih1[j] + bhh1[j];

    const int boff = (role == 3) ? 7 : 0;     // layer0 batch offset

    // zero initial states (both parities)
    for (int idx = tid; idx < 2 * NB * 64; idx += NTHREADS) {
        (&h0buf[0][0][0])[idx] = 0.0f;
        (&h1buf[0][0][0])[idx] = 0.0f;
    }
    // preload x(0)
    if (tid < 2 * NB) {
        int b = tid >> 1, half = tid & 1;
        int bb = b0 + b; if (bb > 2047) bb = 2047;
        float4 v = *reinterpret_cast<const float4*>(x + (size_t)bb * (T_STEPS * 8) + half * 4);
        *reinterpret_cast<float4*>(&xbuf[0][b][half * 4]) = v;
    }
    __syncthreads();

    ull a0[7];     // layer0 partials (roles 0/3)
    ull a1[NB];    // Wih1 partials (role 1)
    ull a2[NB];    // Whh1 partials (role 2)

    // slot it: phase1 computes partials; finalize publishes h0(it), c(it-1), h1(it-2)
    for (int it = 0; it <= T_STEPS + 1; ++it) {
        // ---------------- phase 1: partial matvecs ----------------
        if (role == 0 || role == 3) {
            if (it <= T_STEPS - 1) {
                const float* hr = &h0buf[(it + 1) & 1][boff][0];  // h0(it-1)
#pragma unroll
                for (int b = 0; b < 7; ++b) a0[b] = 0ull;
#pragma unroll
                for (int i = 0; i < 8; ++i) {
                    const ull w0 = wv[2 * i], w1 = wv[2 * i + 1];
#pragma unroll
                    for (int b = 0; b < 7; ++b) {
                        ulonglong2 hv = *reinterpret_cast<const ulonglong2*>(
                            hr + b * 64 + kh * 32 + i * 4);
                        a0[b] = ffma2(w0, hv.x, a0[b]);
                        a0[b] = ffma2(w1, hv.y, a0[b]);
                    }
                }
                if (kh) {
#pragma unroll
                    for (int b = 0; b < 7; ++b) p0[boff + b][j] = a0[b];
                }
            }
        } else if (role == 1) {
            if (it <= T_STEPS) {
                const float* hr = &h0buf[(it + 1) & 1][0][0];     // h0(it-1)
#pragma unroll
                for (int b = 0; b < NB; ++b) a1[b] = 0ull;
#pragma unroll
                for (int i = 0; i < 8; ++i) {
                    const ull w0 = wv[2 * i], w1 = wv[2 * i + 1];
#pragma unroll
                    for (int b = 0; b < NB; ++b) {
                        ulonglong2 hv = *reinterpret_cast<const ulonglong2*>(
                            hr + b * 64 + kh * 32 + i * 4);
                        a1[b] = ffma2(w0, hv.x, a1[b]);
                        a1[b] = ffma2(w1, hv.y, a1[b]);
                    }
                }
                if (kh) {
#pragma unroll
                    for (int b = 0; b < NB; ++b) p1[b][j] = a1[b];
                }
            }
            // x prefetch for step it+1 (28 threads of r1-kh1)
            if (kh && it + 1 <= T_STEPS - 1) {
                int l = tid - 192;
                if (l < 2 * NB) {
                    int b = l >> 1, half = l & 1;
                    int bb = b0 + b; if (bb > 2047) bb = 2047;
                    float4 v = *reinterpret_cast<const float4*>(
                        x + (size_t)bb * (T_STEPS * 8) + (it + 1) * 8 + half * 4);
                    *reinterpret_cast<float4*>(&xbuf[(it + 1) & 1][b][half * 4]) = v;
                }
            }
        } else {  // role 2
            const float* hr = &h1buf[(it + 1) & 1][0][0];         // h1(it-3)
#pragma unroll
            for (int b = 0; b < NB; ++b) a2[b] = 0ull;
#pragma unroll
            for (int i = 0; i < 8; ++i) {
                const ull w0 = wv[2 * i], w1 = wv[2 * i + 1];
#pragma unroll
                for (int b = 0; b < NB; ++b) {
                    ulonglong2 hv = *reinterpret_cast<const ulonglong2*>(
                        hr + b * 64 + kh * 32 + i * 4);
                    a2[b] = ffma2(w0, hv.x, a2[b]);
                    a2[b] = ffma2(w1, hv.y, a2[b]);
                }
            }
            if (kh) {
#pragma unroll
                for (int b = 0; b < NB; ++b) p2[b][j] = a2[b];
            }
        }

        __syncthreads();   // partials + x visible

        // ---------------- finalize: sums / tanh / publish ----------------
        if ((role == 0 || role == 3) && !kh && it <= T_STEPS - 1) {
            const float* xr = &xbuf[it & 1][boff][0];
#pragma unroll
            for (int b = 0; b < 7; ++b) {
                ulonglong2 xv = *reinterpret_cast<const ulonglong2*>(xr + b * 8);
                ulonglong2 xw = *reinterpret_cast<const ulonglong2*>(xr + b * 8 + 4);
                ull acc = ffma2(wx[0], xv.x, a0[b]);
                acc = ffma2(wx[1], xv.y, acc);
                acc = ffma2(wx[2], xw.x, acc);
                acc = ffma2(wx[3], xw.y, acc);
                acc = add2(acc, p0[boff + b][j]);
                h0buf[it & 1][boff + b][j] = tanh_fast(hsum2(acc) + bias0);  // h0(it)
            }
        } else if (role == 1 && !kh && it <= T_STEPS) {
#pragma unroll
            for (int b = 0; b < NB; ++b) {
                ull acc = add2(a1[b], p1[b][j]);
                cbuf[(it + 1) & 1][b][j] = hsum2(acc);                       // c(it-1)
            }
        } else if (role == 2 && !kh && it >= 2) {
            // h1(it-2) = tanh(c(it-2) + Whh1 . h1(it-3) + bias1)
#pragma unroll
            for (int b = 0; b < NB; ++b) {
                ull acc = add2(a2[b], p2[b][j]);
                float pp = hsum2(acc);
                h1buf[it & 1][b][j] = tanh_fast(pp + cbuf[it & 1][b][j] + bias1);
            }
        }

        __syncthreads();   // h0(it), c(it-1), h1(it-2) published
    }

    // final FC: h1(T-1) = h1(511) lives in h1buf[(T_STEPS+1)&1] = h1buf[1]
    if (tid < NB && b0 + tid < 2048) {
        float s = fcb[0];
        const float* hrow = &h1buf[(T_STEPS + 1) & 1][tid][0];
#pragma unroll 16
        for (int k = 0; k < 64; ++k) s += hrow[k] * fcw[k];
        out[b0 + tid] = s;
    }
}

extern "C" void kernel_launch(void* const* d_in, const int* in_sizes, int n_in,
                              void* d_out, int out_size)
{
    const float* x    = (const float*)d_in[0];
    const float* Wih0 = (const float*)d_in[1];
    const float* Whh0 = (const float*)d_in[2];
    const float* bih0 = (const float*)d_in[3];
    const float* bhh0 = (const float*)d_in[4];
    const float* Wih1 = (const float*)d_in[5];
    const float* Whh1 = (const float*)d_in[6];
    const float* bih1 = (const float*)d_in[7];
    const float* bhh1 = (const float*)d_in[8];
    const float* fcw  = (const float*)d_in[9];
    const float* fcb  = (const float*)d_in[10];
    float* out = (float*)d_out;

    rnn_ws_kernel<<<NBLK, NTHREADS>>>(
        x, Wih0, Whh0, bih0, bhh0, Wih1, Whh1, bih1, bhh1, fcw, fcb, out);
}